// round 14
// baseline (speedup 1.0000x reference)
#include <cuda_runtime.h>

#define T_STEPS 1024
#define BATCH   2048
#define N1      30
#define N2      60

using ull = unsigned long long;

// ---- scratch: per-lane y partials; reduced by a second kernel (256 MiB bss) ----
__device__ float2 g_ysc[T_STEPS][BATCH / 2][32];

// packed fp32x2 FMA (Blackwell)
__device__ __forceinline__ ull ffma2(ull a, ull b, ull c) {
    ull d;
    asm("fma.rn.f32x2 %0, %1, %2, %3;" : "=l"(d) : "l"(a), "l"(b), "l"(c));
    return d;
}
__device__ __forceinline__ ull pk2(float x, float y) {
    ull r;
    asm("mov.b64 %0, {%1, %2};" : "=l"(r) : "f"(x), "f"(y));
    return r;
}
__device__ __forceinline__ float hadd2(ull v) {
    float a, b;
    asm("mov.b64 {%0, %1}, %2;" : "=f"(a), "=f"(b) : "l"(v));
    return a + b;
}
// fast tanh, ~1e-6 rel err; pre-activations bounded, no clamp needed
__device__ __forceinline__ float ftanh(float x) {
    float e = __expf(-2.f * x);
    return __fdividef(1.f - e, 1.f + e);
}
// compiler-only memory fence: orders SASS smem ops; warp is convergent, smem is
// in-order per warp, so no runtime barrier needed
__device__ __forceinline__ void cfence() { asm volatile("" ::: "memory"); }

#define W11S 34   // smem row stride for W11

__global__ void __launch_bounds__(128) hier_rnn_kernel(
    const float* __restrict__ inp,    // (T, B, 1)
    const float* __restrict__ noise1, // (T, B, N1)
    const float* __restrict__ noise2, // (T, B, N2)
    const float* __restrict__ W11,    // (N1, N1)
    const float* __restrict__ W22,    // (N2, N2)
    const float* __restrict__ W21,    // (N2, N1)
    const float* __restrict__ M21,    // (N2, N1)
    const float* __restrict__ Win,    // (N1,)
    const float* __restrict__ Wout)   // (N2,)
{
    // per-warp, per-batch-element state buffers (R10 layout)
    __shared__ __align__(16) float s1buf[4][2][32];   // floats 30,31 = write-only pads
    __shared__ __align__(16) float s2buf[4][2][64];   // floats 60..63 = write-only pads
    __shared__ __align__(8)  float sW11[N1][W11S];    // cols 30..33 zero

    const int tid  = threadIdx.x;
    const int warp = tid >> 5;
    const int l    = tid & 31;
    const int gw   = blockIdx.x * 4 + warp;     // batch-pair index
    const int b0   = gw * 2;                    // this warp owns batch b0, b0+1

    float* s1_0 = s1buf[warp][0];
    float* s1_1 = s1buf[warp][1];
    float* s2_0 = s2buf[warp][0];
    float* s2_1 = s2buf[warp][1];

    const bool act = (l < N1);
    const int  ls  = act ? l : 0;       // clamped index for memory/weight addressing
    const int  ra  = 2 * ls;
    const int  rb  = 2 * ls + 1;

    // ---- W21m + W22 in registers (180 regs); W11 in smem ----
    ull w21ap[15], w21bp[15], w22ap[30], w22bp[30];
    #pragma unroll
    for (int k = 0; k < 15; k++) {
        float2 w = act ? *(const float2*)(W21 + ra * N1 + 2 * k) : make_float2(0.f, 0.f);
        float2 m = act ? *(const float2*)(M21 + ra * N1 + 2 * k) : make_float2(0.f, 0.f);
        w21ap[k] = pk2(w.x * m.x, w.y * m.y);
        w = act ? *(const float2*)(W21 + rb * N1 + 2 * k) : make_float2(0.f, 0.f);
        m = act ? *(const float2*)(M21 + rb * N1 + 2 * k) : make_float2(0.f, 0.f);
        w21bp[k] = pk2(w.x * m.x, w.y * m.y);
    }
    #pragma unroll
    for (int k = 0; k < 30; k++) {
        float2 w = act ? *(const float2*)(W22 + ra * N2 + 2 * k) : make_float2(0.f, 0.f);
        w22ap[k] = pk2(w.x, w.y);
        w = act ? *(const float2*)(W22 + rb * N2 + 2 * k) : make_float2(0.f, 0.f);
        w22bp[k] = pk2(w.x, w.y);
    }
    const float winl  = act ? Win[l]   : 0.f;
    const float wouta = act ? Wout[ra] : 0.f;
    const float woutb = act ? Wout[rb] : 0.f;

    // ---- W11 smem table (block-shared) ----
    for (int idx = tid; idx < N1 * W11S; idx += 128) {
        int r = idx / W11S, c = idx - r * W11S;
        sW11[r][c] = (c < N1) ? W11[r * N1 + c] : 0.f;
    }

    // ---- zero state ----
    s1_0[l] = 0.f; s1_1[l] = 0.f;
    s2_0[l] = 0.f; s2_0[l + 32] = 0.f;
    s2_1[l] = 0.f; s2_1[l + 32] = 0.f;
    __syncthreads();

    const float* rw = &sW11[ls][0];

    // ---- streaming pointers ----
    const float* pn1 = noise1 + (long long)b0 * N1 + ls;
    const float* pn2 = noise2 + (long long)b0 * N2 + ra;
    const float* px  = inp + b0;

    float2 xv   = *(const float2*)px;
    float  n1v0 = __ldg(pn1);
    float  n1v1 = __ldg(pn1 + N1);
    float2 n2v0 = *(const float2*)pn2;
    float2 n2v1 = *(const float2*)(pn2 + N2);

    const ulonglong2* v1_0 = (const ulonglong2*)s1_0;
    const ulonglong2* v1_1 = (const ulonglong2*)s1_1;
    const ulonglong2* v2_0 = (const ulonglong2*)s2_0;
    const ulonglong2* v2_1 = (const ulonglong2*)s2_1;
    const ull* s1w_0 = (const ull*)s1_0;
    const ull* s1w_1 = (const ull*)s1_1;

    for (int t = 0; t < T_STEPS; t++) {
        // one-step-ahead prefetch (covers DRAM latency); uniform branch, no divergence
        float2 xn  = make_float2(0.f, 0.f);
        float  n1n0 = 0.f, n1n1 = 0.f;
        float2 n2n0 = make_float2(0.f, 0.f), n2n1 = make_float2(0.f, 0.f);
        if (t + 1 < T_STEPS) {
            px  += BATCH;
            pn1 += BATCH * N1;
            pn2 += BATCH * N2;
            xn   = *(const float2*)px;
            n1n0 = __ldg(pn1);
            n1n1 = __ldg(pn1 + N1);
            n2n0 = *(const float2*)pn2;
            n2n1 = *(const float2*)(pn2 + N2);
        }

        // ---- phase A: W22 . r2_old — 4 independent chains ----
        ull a2a0 = 0, a2b0 = 0, a2a1 = 0, a2b1 = 0;
        #pragma unroll
        for (int k = 0; k < 15; k++) {
            ulonglong2 u0 = v2_0[k];
            ulonglong2 u1 = v2_1[k];
            a2a0 = ffma2(w22ap[2 * k],     u0.x, a2a0);
            a2a0 = ffma2(w22ap[2 * k + 1], u0.y, a2a0);
            a2b0 = ffma2(w22bp[2 * k],     u0.x, a2b0);
            a2b0 = ffma2(w22bp[2 * k + 1], u0.y, a2b0);
            a2a1 = ffma2(w22ap[2 * k],     u1.x, a2a1);
            a2a1 = ffma2(w22ap[2 * k + 1], u1.y, a2a1);
            a2b1 = ffma2(w22bp[2 * k],     u1.x, a2b1);
            a2b1 = ffma2(w22bp[2 * k + 1], u1.y, a2b1);
        }

        // ---- phase B: r1 update, W11 from smem ----
        ull a1_0 = 0, a1_1 = 0;
        #pragma unroll
        for (int k = 0; k < 7; k++) {
            float2 wx = *(const float2*)(rw + 4 * k);
            float2 wy = *(const float2*)(rw + 4 * k + 2);
            ull wX = pk2(wx.x, wx.y), wY = pk2(wy.x, wy.y);
            ulonglong2 u0 = v1_0[k];
            ulonglong2 u1 = v1_1[k];
            a1_0 = ffma2(wX, u0.x, a1_0);
            a1_0 = ffma2(wY, u0.y, a1_0);
            a1_1 = ffma2(wX, u1.x, a1_1);
            a1_1 = ffma2(wY, u1.y, a1_1);
        }
        {
            float2 wt = *(const float2*)(rw + 28);
            ull wT = pk2(wt.x, wt.y);
            a1_0 = ffma2(wT, s1w_0[14], a1_0);
            a1_1 = ffma2(wT, s1w_1[14], a1_1);
        }

        float r1n0 = ftanh(fmaf(winl, xv.x, n1v0) + hadd2(a1_0));
        float r1n1 = ftanh(fmaf(winl, xv.y, n1v1) + hadd2(a1_1));

        cfence();                        // old-s1 reads stay before the publish
        s1_0[l] = r1n0;                  // lanes 30,31 write pads (never read)
        s1_1[l] = r1n1;
        cfence();                        // r1_new publish stays before phase-C reads

        // ---- phase C: += W21m . r1_new ----
        #pragma unroll
        for (int k = 0; k < 7; k++) {
            ulonglong2 u0 = v1_0[k];
            ulonglong2 u1 = v1_1[k];
            a2a0 = ffma2(w21ap[2 * k],     u0.x, a2a0);
            a2b0 = ffma2(w21bp[2 * k],     u0.x, a2b0);
            a2a1 = ffma2(w21ap[2 * k],     u1.x, a2a1);
            a2b1 = ffma2(w21bp[2 * k],     u1.x, a2b1);
            a2a0 = ffma2(w21ap[2 * k + 1], u0.y, a2a0);
            a2b0 = ffma2(w21bp[2 * k + 1], u0.y, a2b0);
            a2a1 = ffma2(w21ap[2 * k + 1], u1.y, a2a1);
            a2b1 = ffma2(w21bp[2 * k + 1], u1.y, a2b1);
        }
        {
            ull u0 = s1w_0[14];
            ull u1 = s1w_1[14];
            a2a0 = ffma2(w21ap[14], u0, a2a0);
            a2b0 = ffma2(w21bp[14], u0, a2b0);
            a2a1 = ffma2(w21ap[14], u1, a2a1);
            a2b1 = ffma2(w21bp[14], u1, a2b1);
        }

        float r2a0 = ftanh(n2v0.x + hadd2(a2a0));
        float r2b0 = ftanh(n2v0.y + hadd2(a2b0));
        float r2a1 = ftanh(n2v1.x + hadd2(a2a1));
        float r2b1 = ftanh(n2v1.y + hadd2(a2b1));

        cfence();                        // old-s2 reads (phase A) stay before publish
        *(float2*)(s2_0 + 2 * l) = make_float2(r2a0, r2b0);   // lanes 30,31 -> pads 60..63
        *(float2*)(s2_1 + 2 * l) = make_float2(r2a1, r2b1);

        // ---- y partials: fire-and-forget streaming store (NO in-loop reduction) ----
        float yp0 = wouta * r2a0 + woutb * r2b0;   // 0 on inactive lanes
        float yp1 = wouta * r2a1 + woutb * r2b1;
        __stcs(&g_ysc[t][gw][l], make_float2(yp0, yp1));

        cfence();                        // publish stays before next step's phase-A reads

        xv = xn; n1v0 = n1n0; n1v1 = n1n1; n2v0 = n2n0; n2v1 = n2n1;
    }
}

// grid-stride reducer: float4 loads, 2 tasks per warp-iteration, half-warp butterfly
__global__ void __launch_bounds__(256) reduce_y(float* __restrict__ out)
{
    const int l      = threadIdx.x & 31;
    const int half   = l >> 4;          // which task of the pair
    const int j      = l & 15;          // float4 index within the task (16 x 16B = 256B)
    const int wid    = (blockIdx.x * blockDim.x + threadIdx.x) >> 5;
    const int nwarps = (gridDim.x * blockDim.x) >> 5;
    const int npairs = T_STEPS * (BATCH / 2) / 2;

    const float4* g4 = (const float4*)g_ysc;

    for (int pair = wid; pair < npairs; pair += nwarps) {
        int task = pair * 2 + half;
        int t    = task >> 10;
        int wp   = task & 1023;
        // float4 = (yp0[2j], yp1[2j], yp0[2j+1], yp1[2j+1])
        float4 v = __ldcs(&g4[(long long)task * 16 + j]);
        float s0 = v.x + v.z;
        float s1 = v.y + v.w;
        #pragma unroll
        for (int o = 8; o > 0; o >>= 1) {
            s0 += __shfl_xor_sync(0xffffffffu, s0, o);
            s1 += __shfl_xor_sync(0xffffffffu, s1, o);
        }
        if (j == 0) *(float2*)(out + t * BATCH + 2 * wp) = make_float2(s0, s1);
    }
}

extern "C" void kernel_launch(void* const* d_in, const int* in_sizes, int n_in,
                              void* d_out, int out_size)
{
    const float *inp = nullptr, *n1 = nullptr, *n2 = nullptr;
    const float *W11 = nullptr, *W22 = nullptr, *W21 = nullptr, *M21 = nullptr;
    const float *Win = nullptr, *Wout = nullptr;

    for (int i = 0; i < n_in; i++) {
        const float* p = (const float*)d_in[i];
        switch (in_sizes[i]) {
            case T_STEPS * BATCH:          inp = p; break;
            case T_STEPS * BATCH * N1:     n1  = p; break;
            case T_STEPS * BATCH * N2:     n2  = p; break;
            case N1 * N1:                  W11 = p; break;
            case N2 * N2:                  W22 = p; break;
            case N2 * N1:                                   // appears twice (W21, mask)
                if (!W21) W21 = p; else M21 = p;            // product commutes
                break;
            case N1:                       Win = p; break;
            case N2:                       Wout = p; break;
        }
    }

    // 256 blocks x 4 warps x 2 batch elements = 2048 (R10 config)
    hier_rnn_kernel<<<BATCH / 8, 128>>>(inp, n1, n2, W11, W22, W21, M21, Win, Wout);
    // persistent grid-stride reduction of the partials
    reduce_y<<<1184, 256>>>((float*)d_out);
}

// round 15
// speedup vs baseline: 1.2543x; 1.2543x over previous
#include <cuda_runtime.h>

#define T_STEPS 1024
#define BATCH   2048
#define N1      30
#define N2      60

using ull = unsigned long long;

// ---- scratch: per-lane y partials; reduced by a second kernel (256 MiB bss) ----
__device__ float2 g_ysc[T_STEPS][BATCH / 2][32];

// packed fp32x2 FMA (Blackwell)
__device__ __forceinline__ ull ffma2(ull a, ull b, ull c) {
    ull d;
    asm("fma.rn.f32x2 %0, %1, %2, %3;" : "=l"(d) : "l"(a), "l"(b), "l"(c));
    return d;
}
__device__ __forceinline__ ull pk2(float x, float y) {
    ull r;
    asm("mov.b64 %0, {%1, %2};" : "=l"(r) : "f"(x), "f"(y));
    return r;
}
__device__ __forceinline__ float hadd2(ull v) {
    float a, b;
    asm("mov.b64 {%0, %1}, %2;" : "=f"(a), "=f"(b) : "l"(v));
    return a + b;
}
// fast tanh, ~1e-6 rel err; pre-activations bounded, no clamp needed
__device__ __forceinline__ float ftanh(float x) {
    float e = __expf(-2.f * x);
    return __fdividef(1.f - e, 1.f + e);
}

#define W11S 34   // smem row stride for W11

__global__ void __launch_bounds__(128) hier_rnn_kernel(
    const float* __restrict__ inp,    // (T, B, 1)
    const float* __restrict__ noise1, // (T, B, N1)
    const float* __restrict__ noise2, // (T, B, N2)
    const float* __restrict__ W11,    // (N1, N1)
    const float* __restrict__ W22,    // (N2, N2)
    const float* __restrict__ W21,    // (N2, N1)
    const float* __restrict__ M21,    // (N2, N1)
    const float* __restrict__ Win,    // (N1,)
    const float* __restrict__ Wout)   // (N2,)
{
    // per-warp, per-batch-element state buffers (R10 layout)
    __shared__ __align__(16) float s1buf[4][2][32];
    __shared__ __align__(16) float s2buf[4][2][64];
    __shared__ __align__(8)  float sW11[N1][W11S];   // cols 30..33 zero

    const int tid  = threadIdx.x;
    const int warp = tid >> 5;
    const int l    = tid & 31;
    const int gw   = blockIdx.x * 4 + warp;     // batch-pair index
    const int b0   = gw * 2;                    // this warp owns batch b0, b0+1

    float* s1_0 = s1buf[warp][0];
    float* s1_1 = s1buf[warp][1];
    float* s2_0 = s2buf[warp][0];
    float* s2_1 = s2buf[warp][1];

    const bool act = (l < N1);
    const int  ls  = act ? l : 0;
    const int  ra  = 2 * ls;
    const int  rb  = 2 * ls + 1;

    // ---- W21m + W22 in registers (180 regs); W11 in smem ----
    ull w21ap[15], w21bp[15], w22ap[30], w22bp[30];
    #pragma unroll
    for (int k = 0; k < 15; k++) {
        float2 w = act ? *(const float2*)(W21 + ra * N1 + 2 * k) : make_float2(0.f, 0.f);
        float2 m = act ? *(const float2*)(M21 + ra * N1 + 2 * k) : make_float2(0.f, 0.f);
        w21ap[k] = pk2(w.x * m.x, w.y * m.y);
        w = act ? *(const float2*)(W21 + rb * N1 + 2 * k) : make_float2(0.f, 0.f);
        m = act ? *(const float2*)(M21 + rb * N1 + 2 * k) : make_float2(0.f, 0.f);
        w21bp[k] = pk2(w.x * m.x, w.y * m.y);
    }
    #pragma unroll
    for (int k = 0; k < 30; k++) {
        float2 w = act ? *(const float2*)(W22 + ra * N2 + 2 * k) : make_float2(0.f, 0.f);
        w22ap[k] = pk2(w.x, w.y);
        w = act ? *(const float2*)(W22 + rb * N2 + 2 * k) : make_float2(0.f, 0.f);
        w22bp[k] = pk2(w.x, w.y);
    }
    const float winl  = act ? Win[l]   : 0.f;
    const float wouta = act ? Wout[ra] : 0.f;
    const float woutb = act ? Wout[rb] : 0.f;

    // ---- W11 smem table (block-shared) ----
    for (int idx = tid; idx < N1 * W11S; idx += 128) {
        int r = idx / W11S, c = idx - r * W11S;
        sW11[r][c] = (c < N1) ? W11[r * N1 + c] : 0.f;
    }

    // ---- zero state ----
    s1_0[l] = 0.f; s1_1[l] = 0.f;
    s2_0[l] = 0.f; s2_0[l + 32] = 0.f;
    s2_1[l] = 0.f; s2_1[l + 32] = 0.f;
    __syncthreads();

    const float* rw = &sW11[ls][0];

    // ---- streaming pointers ----
    const float* pn1 = noise1 + (long long)b0 * N1 + ls;
    const float* pn2 = noise2 + (long long)b0 * N2 + ra;
    const float* px  = inp + b0;

    float2 xv   = *(const float2*)px;
    float  n1v0 = __ldg(pn1);
    float  n1v1 = __ldg(pn1 + N1);
    float2 n2v0 = *(const float2*)pn2;
    float2 n2v1 = *(const float2*)(pn2 + N2);

    const ulonglong2* v1_0 = (const ulonglong2*)s1_0;
    const ulonglong2* v1_1 = (const ulonglong2*)s1_1;
    const ulonglong2* v2_0 = (const ulonglong2*)s2_0;
    const ulonglong2* v2_1 = (const ulonglong2*)s2_1;
    const ull* s1w_0 = (const ull*)s1_0;
    const ull* s1w_1 = (const ull*)s1_1;

    for (int t = 0; t < T_STEPS; t++) {
        // one-step-ahead prefetch (covers DRAM latency)
        float2 xn  = make_float2(0.f, 0.f);
        float  n1n0 = 0.f, n1n1 = 0.f;
        float2 n2n0 = make_float2(0.f, 0.f), n2n1 = make_float2(0.f, 0.f);
        if (t + 1 < T_STEPS) {
            px  += BATCH;
            pn1 += BATCH * N1;
            pn2 += BATCH * N2;
            xn   = *(const float2*)px;
            n1n0 = __ldg(pn1);
            n1n1 = __ldg(pn1 + N1);
            n2n0 = *(const float2*)pn2;
            n2n1 = *(const float2*)(pn2 + N2);
        }

        // ---- phase A: W22 . r2_old — 4 independent chains ----
        ull a2a0 = 0, a2b0 = 0, a2a1 = 0, a2b1 = 0;
        #pragma unroll
        for (int k = 0; k < 15; k++) {
            ulonglong2 u0 = v2_0[k];
            ulonglong2 u1 = v2_1[k];
            a2a0 = ffma2(w22ap[2 * k],     u0.x, a2a0);
            a2a0 = ffma2(w22ap[2 * k + 1], u0.y, a2a0);
            a2b0 = ffma2(w22bp[2 * k],     u0.x, a2b0);
            a2b0 = ffma2(w22bp[2 * k + 1], u0.y, a2b0);
            a2a1 = ffma2(w22ap[2 * k],     u1.x, a2a1);
            a2a1 = ffma2(w22ap[2 * k + 1], u1.y, a2a1);
            a2b1 = ffma2(w22bp[2 * k],     u1.x, a2b1);
            a2b1 = ffma2(w22bp[2 * k + 1], u1.y, a2b1);
        }

        // ---- phase B: r1 update, W11 from smem ----
        ull a1_0 = 0, a1_1 = 0;
        #pragma unroll
        for (int k = 0; k < 7; k++) {
            float2 wx = *(const float2*)(rw + 4 * k);
            float2 wy = *(const float2*)(rw + 4 * k + 2);
            ull wX = pk2(wx.x, wx.y), wY = pk2(wy.x, wy.y);
            ulonglong2 u0 = v1_0[k];
            ulonglong2 u1 = v1_1[k];
            a1_0 = ffma2(wX, u0.x, a1_0);
            a1_0 = ffma2(wY, u0.y, a1_0);
            a1_1 = ffma2(wX, u1.x, a1_1);
            a1_1 = ffma2(wY, u1.y, a1_1);
        }
        {
            float2 wt = *(const float2*)(rw + 28);
            ull wT = pk2(wt.x, wt.y);
            a1_0 = ffma2(wT, s1w_0[14], a1_0);
            a1_1 = ffma2(wT, s1w_1[14], a1_1);
        }

        float r1n0 = ftanh(fmaf(winl, xv.x, n1v0) + hadd2(a1_0));
        float r1n1 = ftanh(fmaf(winl, xv.y, n1v1) + hadd2(a1_1));

        __syncwarp();                    // all old-state reads done
        if (act) { s1_0[l] = r1n0; s1_1[l] = r1n1; }
        __syncwarp();                    // r1_new visible

        // ---- phase C: += W21m . r1_new ----
        #pragma unroll
        for (int k = 0; k < 7; k++) {
            ulonglong2 u0 = v1_0[k];
            ulonglong2 u1 = v1_1[k];
            a2a0 = ffma2(w21ap[2 * k],     u0.x, a2a0);
            a2b0 = ffma2(w21bp[2 * k],     u0.x, a2b0);
            a2a1 = ffma2(w21ap[2 * k],     u1.x, a2a1);
            a2b1 = ffma2(w21bp[2 * k],     u1.x, a2b1);
            a2a0 = ffma2(w21ap[2 * k + 1], u0.y, a2a0);
            a2b0 = ffma2(w21bp[2 * k + 1], u0.y, a2b0);
            a2a1 = ffma2(w21ap[2 * k + 1], u1.y, a2a1);
            a2b1 = ffma2(w21bp[2 * k + 1], u1.y, a2b1);
        }
        {
            ull u0 = s1w_0[14];
            ull u1 = s1w_1[14];
            a2a0 = ffma2(w21ap[14], u0, a2a0);
            a2b0 = ffma2(w21bp[14], u0, a2b0);
            a2a1 = ffma2(w21ap[14], u1, a2a1);
            a2b1 = ffma2(w21bp[14], u1, a2b1);
        }

        float r2a0 = ftanh(n2v0.x + hadd2(a2a0));
        float r2b0 = ftanh(n2v0.y + hadd2(a2b0));
        float r2a1 = ftanh(n2v1.x + hadd2(a2a1));
        float r2b1 = ftanh(n2v1.y + hadd2(a2b1));

        __syncwarp();                    // order publish after old-r2 reads
        if (act) {
            *(float2*)(s2_0 + ra) = make_float2(r2a0, r2b0);
            *(float2*)(s2_1 + ra) = make_float2(r2a1, r2b1);
        }

        // ---- y partials: fire-and-forget streaming store (NO in-loop reduction) ----
        float yp0 = wouta * r2a0 + woutb * r2b0;   // 0 on inactive lanes
        float yp1 = wouta * r2a1 + woutb * r2b1;
        __stcs(&g_ysc[t][gw][l], make_float2(yp0, yp1));

        __syncwarp();                    // publishes visible before next step's reads

        xv = xn; n1v0 = n1n0; n1v1 = n1n1; n2v0 = n2n0; n2v1 = n2n1;
    }
}

// grid-stride reducer: float4 loads, 2 tasks per warp-iteration, half-warp butterfly
__global__ void __launch_bounds__(256) reduce_y(float* __restrict__ out)
{
    const int l      = threadIdx.x & 31;
    const int half   = l >> 4;          // which task of the pair
    const int j      = l & 15;          // float4 index within the task (16 x 16B = 256B)
    const int wid    = (blockIdx.x * blockDim.x + threadIdx.x) >> 5;
    const int nwarps = (gridDim.x * blockDim.x) >> 5;
    const int npairs = T_STEPS * (BATCH / 2) / 2;

    const float4* g4 = (const float4*)g_ysc;

    for (int pair = wid; pair < npairs; pair += nwarps) {
        int task = pair * 2 + half;
        int t    = task >> 10;
        int wp   = task & 1023;
        // float4 = (yp0[2j], yp1[2j], yp0[2j+1], yp1[2j+1])
        float4 v = __ldcs(&g4[(long long)task * 16 + j]);
        float s0 = v.x + v.z;
        float s1 = v.y + v.w;
        #pragma unroll
        for (int o = 8; o > 0; o >>= 1) {
            s0 += __shfl_xor_sync(0xffffffffu, s0, o);
            s1 += __shfl_xor_sync(0xffffffffu, s1, o);
        }
        if (j == 0) *(float2*)(out + t * BATCH + 2 * wp) = make_float2(s0, s1);
    }
}

extern "C" void kernel_launch(void* const* d_in, const int* in_sizes, int n_in,
                              void* d_out, int out_size)
{
    const float *inp = nullptr, *n1 = nullptr, *n2 = nullptr;
    const float *W11 = nullptr, *W22 = nullptr, *W21 = nullptr, *M21 = nullptr;
    const float *Win = nullptr, *Wout = nullptr;

    for (int i = 0; i < n_in; i++) {
        const float* p = (const float*)d_in[i];
        switch (in_sizes[i]) {
            case T_STEPS * BATCH:          inp = p; break;
            case T_STEPS * BATCH * N1:     n1  = p; break;
            case T_STEPS * BATCH * N2:     n2  = p; break;
            case N1 * N1:                  W11 = p; break;
            case N2 * N2:                  W22 = p; break;
            case N2 * N1:                                   // appears twice (W21, mask)
                if (!W21) W21 = p; else M21 = p;            // product commutes
                break;
            case N1:                       Win = p; break;
            case N2:                       Wout = p; break;
        }
    }

    // 256 blocks x 4 warps x 2 batch elements = 2048 (R10 config)
    hier_rnn_kernel<<<BATCH / 8, 128>>>(inp, n1, n2, W11, W22, W21, M21, Win, Wout);
    // persistent grid-stride reduction of the partials
    reduce_y<<<1184, 256>>>((float*)d_out);
}

// round 16
// speedup vs baseline: 1.4039x; 1.1192x over previous
#include <cuda_runtime.h>

#define T_STEPS 1024
#define BATCH   2048
#define N1      30
#define N2      60

using ull = unsigned long long;

// packed fp32x2 FMA (Blackwell)
__device__ __forceinline__ ull ffma2(ull a, ull b, ull c) {
    ull d;
    asm("fma.rn.f32x2 %0, %1, %2, %3;" : "=l"(d) : "l"(a), "l"(b), "l"(c));
    return d;
}
__device__ __forceinline__ ull pk2(float x, float y) {
    ull r;
    asm("mov.b64 %0, {%1, %2};" : "=l"(r) : "f"(x), "f"(y));
    return r;
}
__device__ __forceinline__ float hadd2(ull v) {
    float a, b;
    asm("mov.b64 {%0, %1}, %2;" : "=f"(a), "=f"(b) : "l"(v));
    return a + b;
}
// fast tanh, ~1e-6 rel err; pre-activations bounded, no clamp needed
__device__ __forceinline__ float ftanh(float x) {
    float e = __expf(-2.f * x);
    return __fdividef(1.f - e, 1.f + e);
}

#define W11S 34   // smem row stride for W11

__global__ void __launch_bounds__(128) hier_rnn_kernel(
    const float* __restrict__ inp,    // (T, B, 1)
    const float* __restrict__ noise1, // (T, B, N1)
    const float* __restrict__ noise2, // (T, B, N2)
    const float* __restrict__ W11,    // (N1, N1)
    const float* __restrict__ W22,    // (N2, N2)
    const float* __restrict__ W21,    // (N2, N1)
    const float* __restrict__ M21,    // (N2, N1)
    const float* __restrict__ Win,    // (N1,)
    const float* __restrict__ Wout,   // (N2,)
    float* __restrict__ out)          // (T, B, 1)
{
    // per-warp, per-batch-element state buffers (R10 layout)
    __shared__ __align__(16) float s1buf[4][2][32];
    __shared__ __align__(16) float s2buf[4][2][64];
    __shared__ __align__(8)  float sW11[N1][W11S];   // cols 30..33 zero

    const int tid  = threadIdx.x;
    const int warp = tid >> 5;
    const int l    = tid & 31;
    const int gw   = blockIdx.x * 4 + warp;     // batch-pair index
    const int b0   = gw * 2;                    // this warp owns batch b0, b0+1

    float* s1_0 = s1buf[warp][0];
    float* s1_1 = s1buf[warp][1];
    float* s2_0 = s2buf[warp][0];
    float* s2_1 = s2buf[warp][1];

    const bool act = (l < N1);
    const int  ls  = act ? l : 0;
    const int  ra  = 2 * ls;
    const int  rb  = 2 * ls + 1;

    // ---- W21m + W22 in registers (180 regs); W11 in smem ----
    // Lane 30's w22ap slots carry the PACKED WOUT PAIRS: its phase-A chain then
    // computes y = wout . r2_old for free (phase C adds 0 there; w21 weights are 0).
    ull w21ap[15], w21bp[15], w22ap[30], w22bp[30];
    #pragma unroll
    for (int k = 0; k < 15; k++) {
        float2 w = act ? *(const float2*)(W21 + ra * N1 + 2 * k) : make_float2(0.f, 0.f);
        float2 m = act ? *(const float2*)(M21 + ra * N1 + 2 * k) : make_float2(0.f, 0.f);
        w21ap[k] = pk2(w.x * m.x, w.y * m.y);
        w = act ? *(const float2*)(W21 + rb * N1 + 2 * k) : make_float2(0.f, 0.f);
        m = act ? *(const float2*)(M21 + rb * N1 + 2 * k) : make_float2(0.f, 0.f);
        w21bp[k] = pk2(w.x * m.x, w.y * m.y);
    }
    #pragma unroll
    for (int k = 0; k < 30; k++) {
        float2 wa = make_float2(0.f, 0.f), wb = make_float2(0.f, 0.f);
        if (act) {
            wa = *(const float2*)(W22 + ra * N2 + 2 * k);
            wb = *(const float2*)(W22 + rb * N2 + 2 * k);
        } else if (l == 30) {
            wa = *(const float2*)(Wout + 2 * k);   // packed wout pairs -> y chain
        }
        w22ap[k] = pk2(wa.x, wa.y);
        w22bp[k] = pk2(wb.x, wb.y);
    }
    const float winl = act ? Win[l] : 0.f;

    // ---- W11 smem table (block-shared) ----
    for (int idx = tid; idx < N1 * W11S; idx += 128) {
        int r = idx / W11S, c = idx - r * W11S;
        sW11[r][c] = (c < N1) ? W11[r * N1 + c] : 0.f;
    }

    // ---- zero state ----
    s1_0[l] = 0.f; s1_1[l] = 0.f;
    s2_0[l] = 0.f; s2_0[l + 32] = 0.f;
    s2_1[l] = 0.f; s2_1[l + 32] = 0.f;
    __syncthreads();

    const float* rw = &sW11[ls][0];

    // ---- streaming pointers ----
    const float* pn1 = noise1 + (long long)b0 * N1 + ls;
    const float* pn2 = noise2 + (long long)b0 * N2 + ra;
    const float* px  = inp + b0;

    float2 xv   = *(const float2*)px;
    float  n1v0 = __ldg(pn1);
    float  n1v1 = __ldg(pn1 + N1);
    float2 n2v0 = *(const float2*)pn2;
    float2 n2v1 = *(const float2*)(pn2 + N2);

    const ulonglong2* v1_0 = (const ulonglong2*)s1_0;
    const ulonglong2* v1_1 = (const ulonglong2*)s1_1;
    const ulonglong2* v2_0 = (const ulonglong2*)s2_0;
    const ulonglong2* v2_1 = (const ulonglong2*)s2_1;
    const ull* s1w_0 = (const ull*)s1_0;
    const ull* s1w_1 = (const ull*)s1_1;

    for (int t = 0; t < T_STEPS; t++) {
        // one-step-ahead prefetch (covers DRAM latency)
        float2 xn  = make_float2(0.f, 0.f);
        float  n1n0 = 0.f, n1n1 = 0.f;
        float2 n2n0 = make_float2(0.f, 0.f), n2n1 = make_float2(0.f, 0.f);
        if (t + 1 < T_STEPS) {
            px  += BATCH;
            pn1 += BATCH * N1;
            pn2 += BATCH * N2;
            xn   = *(const float2*)px;
            n1n0 = __ldg(pn1);
            n1n1 = __ldg(pn1 + N1);
            n2n0 = *(const float2*)pn2;
            n2n1 = *(const float2*)(pn2 + N2);
        }

        // ---- phase A: W22 . r2_old — 4 independent chains ----
        // (lane 30: a2a0/a2a1 compute wout . r2_old = y(t-1) for elems 0/1)
        ull a2a0 = 0, a2b0 = 0, a2a1 = 0, a2b1 = 0;
        #pragma unroll
        for (int k = 0; k < 15; k++) {
            ulonglong2 u0 = v2_0[k];
            ulonglong2 u1 = v2_1[k];
            a2a0 = ffma2(w22ap[2 * k],     u0.x, a2a0);
            a2a0 = ffma2(w22ap[2 * k + 1], u0.y, a2a0);
            a2b0 = ffma2(w22bp[2 * k],     u0.x, a2b0);
            a2b0 = ffma2(w22bp[2 * k + 1], u0.y, a2b0);
            a2a1 = ffma2(w22ap[2 * k],     u1.x, a2a1);
            a2a1 = ffma2(w22ap[2 * k + 1], u1.y, a2a1);
            a2b1 = ffma2(w22bp[2 * k],     u1.x, a2b1);
            a2b1 = ffma2(w22bp[2 * k + 1], u1.y, a2b1);
        }

        // ---- phase B: r1 update, W11 from smem ----
        ull a1_0 = 0, a1_1 = 0;
        #pragma unroll
        for (int k = 0; k < 7; k++) {
            float2 wx = *(const float2*)(rw + 4 * k);
            float2 wy = *(const float2*)(rw + 4 * k + 2);
            ull wX = pk2(wx.x, wx.y), wY = pk2(wy.x, wy.y);
            ulonglong2 u0 = v1_0[k];
            ulonglong2 u1 = v1_1[k];
            a1_0 = ffma2(wX, u0.x, a1_0);
            a1_0 = ffma2(wY, u0.y, a1_0);
            a1_1 = ffma2(wX, u1.x, a1_1);
            a1_1 = ffma2(wY, u1.y, a1_1);
        }
        {
            float2 wt = *(const float2*)(rw + 28);
            ull wT = pk2(wt.x, wt.y);
            a1_0 = ffma2(wT, s1w_0[14], a1_0);
            a1_1 = ffma2(wT, s1w_1[14], a1_1);
        }

        float r1n0 = ftanh(fmaf(winl, xv.x, n1v0) + hadd2(a1_0));
        float r1n1 = ftanh(fmaf(winl, xv.y, n1v1) + hadd2(a1_1));

        __syncwarp();                    // all old-state reads done
        if (act) { s1_0[l] = r1n0; s1_1[l] = r1n1; }
        __syncwarp();                    // r1_new visible

        // ---- phase C: += W21m . r1_new  (adds 0 on lane 30 -> y chains intact) ----
        #pragma unroll
        for (int k = 0; k < 7; k++) {
            ulonglong2 u0 = v1_0[k];
            ulonglong2 u1 = v1_1[k];
            a2a0 = ffma2(w21ap[2 * k],     u0.x, a2a0);
            a2b0 = ffma2(w21bp[2 * k],     u0.x, a2b0);
            a2a1 = ffma2(w21ap[2 * k],     u1.x, a2a1);
            a2b1 = ffma2(w21bp[2 * k],     u1.x, a2b1);
            a2a0 = ffma2(w21ap[2 * k + 1], u0.y, a2a0);
            a2b0 = ffma2(w21bp[2 * k + 1], u0.y, a2b0);
            a2a1 = ffma2(w21ap[2 * k + 1], u1.y, a2a1);
            a2b1 = ffma2(w21bp[2 * k + 1], u1.y, a2b1);
        }
        {
            ull u0 = s1w_0[14];
            ull u1 = s1w_1[14];
            a2a0 = ffma2(w21ap[14], u0, a2a0);
            a2b0 = ffma2(w21bp[14], u0, a2b0);
            a2a1 = ffma2(w21ap[14], u1, a2a1);
            a2b1 = ffma2(w21bp[14], u1, a2b1);
        }

        float sa0 = hadd2(a2a0);         // lane 30: y(t-1) elem0
        float sa1 = hadd2(a2a1);         // lane 30: y(t-1) elem1
        float r2a0 = ftanh(n2v0.x + sa0);
        float r2b0 = ftanh(n2v0.y + hadd2(a2b0));
        float r2a1 = ftanh(n2v1.x + sa1);
        float r2b1 = ftanh(n2v1.y + hadd2(a2b1));

        __syncwarp();                    // order publish after old-r2 reads
        if (act) {
            *(float2*)(s2_0 + ra) = make_float2(r2a0, r2b0);
            *(float2*)(s2_1 + ra) = make_float2(r2a1, r2b1);
        }

        // ---- y(t-1) store from lane 30 (predicated; no shuffles, no scratch) ----
        if (l == 30 && t > 0)
            __stcs((float2*)(out + (t - 1) * BATCH + b0), make_float2(sa0, sa1));

        __syncwarp();                    // publishes visible before next step's reads

        xv = xn; n1v0 = n1n0; n1v1 = n1n1; n2v0 = n2n0; n2v1 = n2n1;
    }

    // ---- epilogue: y(T-1) = wout . r2(T-1), one extra phase-A-style pass ----
    ull e0 = 0, e1 = 0;
    #pragma unroll
    for (int k = 0; k < 15; k++) {
        ulonglong2 u0 = v2_0[k];
        ulonglong2 u1 = v2_1[k];
        e0 = ffma2(w22ap[2 * k],     u0.x, e0);
        e0 = ffma2(w22ap[2 * k + 1], u0.y, e0);
        e1 = ffma2(w22ap[2 * k],     u1.x, e1);
        e1 = ffma2(w22ap[2 * k + 1], u1.y, e1);
    }
    if (l == 30)
        __stcs((float2*)(out + (T_STEPS - 1) * BATCH + b0),
               make_float2(hadd2(e0), hadd2(e1)));
}

extern "C" void kernel_launch(void* const* d_in, const int* in_sizes, int n_in,
                              void* d_out, int out_size)
{
    const float *inp = nullptr, *n1 = nullptr, *n2 = nullptr;
    const float *W11 = nullptr, *W22 = nullptr, *W21 = nullptr, *M21 = nullptr;
    const float *Win = nullptr, *Wout = nullptr;

    for (int i = 0; i < n_in; i++) {
        const float* p = (const float*)d_in[i];
        switch (in_sizes[i]) {
            case T_STEPS * BATCH:          inp = p; break;
            case T_STEPS * BATCH * N1:     n1  = p; break;
            case T_STEPS * BATCH * N2:     n2  = p; break;
            case N1 * N1:                  W11 = p; break;
            case N2 * N2:                  W22 = p; break;
            case N2 * N1:                                   // appears twice (W21, mask)
                if (!W21) W21 = p; else M21 = p;            // product commutes
                break;
            case N1:                       Win = p; break;
            case N2:                       Wout = p; break;
        }
    }

    // 256 blocks x 4 warps x 2 batch elements = 2048; single kernel, no reducer
    hier_rnn_kernel<<<BATCH / 8, 128>>>(inp, n1, n2, W11, W22, W21, M21, Win, Wout,
                                        (float*)d_out);
}

// round 17
// speedup vs baseline: 1.4084x; 1.0032x over previous
#include <cuda_runtime.h>

#define T_STEPS 1024
#define BATCH   2048
#define N1      30
#define N2      60

using ull = unsigned long long;

// packed fp32x2 FMA (Blackwell)
__device__ __forceinline__ ull ffma2(ull a, ull b, ull c) {
    ull d;
    asm("fma.rn.f32x2 %0, %1, %2, %3;" : "=l"(d) : "l"(a), "l"(b), "l"(c));
    return d;
}
__device__ __forceinline__ ull pk2(float x, float y) {
    ull r;
    asm("mov.b64 %0, {%1, %2};" : "=l"(r) : "f"(x), "f"(y));
    return r;
}
__device__ __forceinline__ float hadd2(ull v) {
    float a, b;
    asm("mov.b64 {%0, %1}, %2;" : "=f"(a), "=f"(b) : "l"(v));
    return a + b;
}
// fast tanh, ~1e-6 rel err; pre-activations bounded, no clamp needed
__device__ __forceinline__ float ftanh(float x) {
    float e = __expf(-2.f * x);
    return __fdividef(1.f - e, 1.f + e);
}

#define W11S 34   // smem row stride for W11

__global__ void __launch_bounds__(128) hier_rnn_kernel(
    const float* __restrict__ inp,    // (T, B, 1)
    const float* __restrict__ noise1, // (T, B, N1)
    const float* __restrict__ noise2, // (T, B, N2)
    const float* __restrict__ W11,    // (N1, N1)
    const float* __restrict__ W22,    // (N2, N2)
    const float* __restrict__ W21,    // (N2, N1)
    const float* __restrict__ M21,    // (N2, N1)
    const float* __restrict__ Win,    // (N1,)
    const float* __restrict__ Wout,   // (N2,)
    float* __restrict__ out)          // (T, B, 1)
{
    // per-warp, per-batch-element state buffers (R10 layout)
    __shared__ __align__(16) float s1buf[4][2][32];
    __shared__ __align__(16) float s2buf[4][2][64];
    __shared__ __align__(8)  float sW11[N1][W11S];   // cols 30..33 zero
    // masked W21 ODD rows (rb = 2l+1), packed pairs, k-interleaved:
    // sw21b[k][l] = pk2(W21m[2l+1][2k], W21m[2l+1][2k+1]); lanes 30,31 = 0.
    // Lane reads are 32 x 8B consecutive -> 2 conflict-free wavefronts.
    __shared__ __align__(16) ull sw21b[15][32];

    const int tid  = threadIdx.x;
    const int warp = tid >> 5;
    const int l    = tid & 31;
    const int gw   = blockIdx.x * 4 + warp;     // batch-pair index
    const int b0   = gw * 2;                    // this warp owns batch b0, b0+1

    float* s1_0 = s1buf[warp][0];
    float* s1_1 = s1buf[warp][1];
    float* s2_0 = s2buf[warp][0];
    float* s2_1 = s2buf[warp][1];

    const bool act = (l < N1);
    const int  ls  = act ? l : 0;
    const int  ra  = 2 * ls;
    const int  rb  = 2 * ls + 1;

    // ---- weights in registers: w21ap (30) + w22ap/bp (120) = 150 regs ----
    // Lane 30's w22ap slots carry the PACKED WOUT PAIRS: its phase-A chain then
    // computes y = wout . r2_old for free (phase C adds 0 there; w21 weights are 0).
    ull w21ap[15], w22ap[30], w22bp[30];
    #pragma unroll
    for (int k = 0; k < 15; k++) {
        float2 w = act ? *(const float2*)(W21 + ra * N1 + 2 * k) : make_float2(0.f, 0.f);
        float2 m = act ? *(const float2*)(M21 + ra * N1 + 2 * k) : make_float2(0.f, 0.f);
        w21ap[k] = pk2(w.x * m.x, w.y * m.y);
    }
    // warp 0 fills the shared W21m odd-row table (identical for all warps)
    if (tid < 32) {
        #pragma unroll
        for (int k = 0; k < 15; k++) {
            float2 w = act ? *(const float2*)(W21 + rb * N1 + 2 * k) : make_float2(0.f, 0.f);
            float2 m = act ? *(const float2*)(M21 + rb * N1 + 2 * k) : make_float2(0.f, 0.f);
            sw21b[k][l] = pk2(w.x * m.x, w.y * m.y);
        }
    }
    #pragma unroll
    for (int k = 0; k < 30; k++) {
        float2 wa = make_float2(0.f, 0.f), wb = make_float2(0.f, 0.f);
        if (act) {
            wa = *(const float2*)(W22 + ra * N2 + 2 * k);
            wb = *(const float2*)(W22 + rb * N2 + 2 * k);
        } else if (l == 30) {
            wa = *(const float2*)(Wout + 2 * k);   // packed wout pairs -> y chain
        }
        w22ap[k] = pk2(wa.x, wa.y);
        w22bp[k] = pk2(wb.x, wb.y);
    }
    const float winl = act ? Win[l] : 0.f;

    // ---- W11 smem table (block-shared) ----
    for (int idx = tid; idx < N1 * W11S; idx += 128) {
        int r = idx / W11S, c = idx - r * W11S;
        sW11[r][c] = (c < N1) ? W11[r * N1 + c] : 0.f;
    }

    // ---- zero state ----
    s1_0[l] = 0.f; s1_1[l] = 0.f;
    s2_0[l] = 0.f; s2_0[l + 32] = 0.f;
    s2_1[l] = 0.f; s2_1[l + 32] = 0.f;
    __syncthreads();

    const float* rw = &sW11[ls][0];

    // ---- streaming pointers ----
    const float* pn1 = noise1 + (long long)b0 * N1 + ls;
    const float* pn2 = noise2 + (long long)b0 * N2 + ra;
    const float* px  = inp + b0;

    float2 xv   = *(const float2*)px;
    float  n1v0 = __ldg(pn1);
    float  n1v1 = __ldg(pn1 + N1);
    float2 n2v0 = *(const float2*)pn2;
    float2 n2v1 = *(const float2*)(pn2 + N2);

    const ulonglong2* v1_0 = (const ulonglong2*)s1_0;
    const ulonglong2* v1_1 = (const ulonglong2*)s1_1;
    const ulonglong2* v2_0 = (const ulonglong2*)s2_0;
    const ulonglong2* v2_1 = (const ulonglong2*)s2_1;
    const ull* s1w_0 = (const ull*)s1_0;
    const ull* s1w_1 = (const ull*)s1_1;

    for (int t = 0; t < T_STEPS; t++) {
        // one-step-ahead prefetch (covers DRAM latency)
        float2 xn  = make_float2(0.f, 0.f);
        float  n1n0 = 0.f, n1n1 = 0.f;
        float2 n2n0 = make_float2(0.f, 0.f), n2n1 = make_float2(0.f, 0.f);
        if (t + 1 < T_STEPS) {
            px  += BATCH;
            pn1 += BATCH * N1;
            pn2 += BATCH * N2;
            xn   = *(const float2*)px;
            n1n0 = __ldg(pn1);
            n1n1 = __ldg(pn1 + N1);
            n2n0 = *(const float2*)pn2;
            n2n1 = *(const float2*)(pn2 + N2);
        }

        // ---- phase A: W22 . r2_old — 4 independent chains ----
        // (lane 30: a2a0/a2a1 compute wout . r2_old = y(t-1) for elems 0/1)
        ull a2a0 = 0, a2b0 = 0, a2a1 = 0, a2b1 = 0;
        #pragma unroll
        for (int k = 0; k < 15; k++) {
            ulonglong2 u0 = v2_0[k];
            ulonglong2 u1 = v2_1[k];
            a2a0 = ffma2(w22ap[2 * k],     u0.x, a2a0);
            a2a0 = ffma2(w22ap[2 * k + 1], u0.y, a2a0);
            a2b0 = ffma2(w22bp[2 * k],     u0.x, a2b0);
            a2b0 = ffma2(w22bp[2 * k + 1], u0.y, a2b0);
            a2a1 = ffma2(w22ap[2 * k],     u1.x, a2a1);
            a2a1 = ffma2(w22ap[2 * k + 1], u1.y, a2a1);
            a2b1 = ffma2(w22bp[2 * k],     u1.x, a2b1);
            a2b1 = ffma2(w22bp[2 * k + 1], u1.y, a2b1);
        }

        // ---- phase B: r1 update, W11 from smem ----
        ull a1_0 = 0, a1_1 = 0;
        #pragma unroll
        for (int k = 0; k < 7; k++) {
            float2 wx = *(const float2*)(rw + 4 * k);
            float2 wy = *(const float2*)(rw + 4 * k + 2);
            ull wX = pk2(wx.x, wx.y), wY = pk2(wy.x, wy.y);
            ulonglong2 u0 = v1_0[k];
            ulonglong2 u1 = v1_1[k];
            a1_0 = ffma2(wX, u0.x, a1_0);
            a1_0 = ffma2(wY, u0.y, a1_0);
            a1_1 = ffma2(wX, u1.x, a1_1);
            a1_1 = ffma2(wY, u1.y, a1_1);
        }
        {
            float2 wt = *(const float2*)(rw + 28);
            ull wT = pk2(wt.x, wt.y);
            a1_0 = ffma2(wT, s1w_0[14], a1_0);
            a1_1 = ffma2(wT, s1w_1[14], a1_1);
        }

        float r1n0 = ftanh(fmaf(winl, xv.x, n1v0) + hadd2(a1_0));
        float r1n1 = ftanh(fmaf(winl, xv.y, n1v1) + hadd2(a1_1));

        __syncwarp();                    // all old-state reads done
        if (act) { s1_0[l] = r1n0; s1_1[l] = r1n1; }
        __syncwarp();                    // r1_new visible

        // ---- phase C: += W21m . r1_new  (odd rows from smem; lane 30 adds 0) ----
        #pragma unroll
        for (int k = 0; k < 7; k++) {
            ull wbx = sw21b[2 * k][l];
            ull wby = sw21b[2 * k + 1][l];
            ulonglong2 u0 = v1_0[k];
            ulonglong2 u1 = v1_1[k];
            a2a0 = ffma2(w21ap[2 * k],     u0.x, a2a0);
            a2b0 = ffma2(wbx,              u0.x, a2b0);
            a2a1 = ffma2(w21ap[2 * k],     u1.x, a2a1);
            a2b1 = ffma2(wbx,              u1.x, a2b1);
            a2a0 = ffma2(w21ap[2 * k + 1], u0.y, a2a0);
            a2b0 = ffma2(wby,              u0.y, a2b0);
            a2a1 = ffma2(w21ap[2 * k + 1], u1.y, a2a1);
            a2b1 = ffma2(wby,              u1.y, a2b1);
        }
        {
            ull wbt = sw21b[14][l];
            ull u0  = s1w_0[14];
            ull u1  = s1w_1[14];
            a2a0 = ffma2(w21ap[14], u0, a2a0);
            a2b0 = ffma2(wbt,       u0, a2b0);
            a2a1 = ffma2(w21ap[14], u1, a2a1);
            a2b1 = ffma2(wbt,       u1, a2b1);
        }

        float sa0 = hadd2(a2a0);         // lane 30: y(t-1) elem0
        float sa1 = hadd2(a2a1);         // lane 30: y(t-1) elem1
        float r2a0 = ftanh(n2v0.x + sa0);
        float r2b0 = ftanh(n2v0.y + hadd2(a2b0));
        float r2a1 = ftanh(n2v1.x + sa1);
        float r2b1 = ftanh(n2v1.y + hadd2(a2b1));

        __syncwarp();                    // order publish after old-r2 reads
        if (act) {
            *(float2*)(s2_0 + ra) = make_float2(r2a0, r2b0);
            *(float2*)(s2_1 + ra) = make_float2(r2a1, r2b1);
        }

        // ---- y(t-1) store from lane 30 (predicated; no shuffles, no scratch) ----
        if (l == 30 && t > 0)
            __stcs((float2*)(out + (t - 1) * BATCH + b0), make_float2(sa0, sa1));

        __syncwarp();                    // publishes visible before next step's reads

        xv = xn; n1v0 = n1n0; n1v1 = n1n1; n2v0 = n2n0; n2v1 = n2n1;
    }

    // ---- epilogue: y(T-1) = wout . r2(T-1), one extra phase-A-style pass ----
    ull e0 = 0, e1 = 0;
    #pragma unroll
    for (int k = 0; k < 15; k++) {
        ulonglong2 u0 = v2_0[k];
        ulonglong2 u1 = v2_1[k];
        e0 = ffma2(w22ap[2 * k],     u0.x, e0);
        e0 = ffma2(w22ap[2 * k + 1], u0.y, e0);
        e1 = ffma2(w22ap[2 * k],     u1.x, e1);
        e1 = ffma2(w22ap[2 * k + 1], u1.y, e1);
    }
    if (l == 30)
        __stcs((float2*)(out + (T_STEPS - 1) * BATCH + b0),
               make_float2(hadd2(e0), hadd2(e1)));
}

extern "C" void kernel_launch(void* const* d_in, const int* in_sizes, int n_in,
                              void* d_out, int out_size)
{
    const float *inp = nullptr, *n1 = nullptr, *n2 = nullptr;
    const float *W11 = nullptr, *W22 = nullptr, *W21 = nullptr, *M21 = nullptr;
    const float *Win = nullptr, *Wout = nullptr;

    for (int i = 0; i < n_in; i++) {
        const float* p = (const float*)d_in[i];
        switch (in_sizes[i]) {
            case T_STEPS * BATCH:          inp = p; break;
            case T_STEPS * BATCH * N1:     n1  = p; break;
            case T_STEPS * BATCH * N2:     n2  = p; break;
            case N1 * N1:                  W11 = p; break;
            case N2 * N2:                  W22 = p; break;
            case N2 * N1:                                   // appears twice (W21, mask)
                if (!W21) W21 = p; else M21 = p;            // product commutes
                break;
            case N1:                       Win = p; break;
            case N2:                       Wout = p; break;
        }
    }

    // 256 blocks x 4 warps x 2 batch elements = 2048; single kernel, no reducer
    hier_rnn_kernel<<<BATCH / 8, 128>>>(inp, n1, n2, W11, W22, W21, M21, Win, Wout,
                                        (float*)d_out);
}